// round 2
// baseline (speedup 1.0000x reference)
#include <cuda_runtime.h>
#include <math.h>

// ---------------------------------------------------------------------------
// HMM forward (CgpHmmCell, nCodons=2): N_STATES=24, CTX=6, N_EMIT=17
// Warp-per-batch, lane-per-state, sparse (in-degree<=4) transition matvec via
// shfl, deferred power-of-two renormalization every 16 steps.
// ---------------------------------------------------------------------------

#define NSTATES 24

// --- precomputed model tables (built by setup_kernel every launch) ----------
__device__ float4 g_W4[32];          // per-lane incoming-edge weights (pad 0)
__device__ float  g_Bt[216 * 32];    // emission: Bt[ctx][lane], lanes>=24 -> 0
__device__ float  g_pi[32];          // softmax(init), lanes>=24 -> 0

// --- static structure tables ------------------------------------------------
// row softmax structure of A (24 rows, up to 4 nonzero cols per row)
__constant__ int c_rcnt[24] = {2,1,1,4,1,1,3,1,1,2,1,1,1,2,1,1,2,1,1,2,1,1,2,1};
__constant__ int c_rcols[24][4] = {
  {0,1,0,0},{2,0,0,0},{3,0,0,0},{4,14,7,10},{5,0,0,0},{6,0,0,0},{7,17,10,0},
  {8,0,0,0},{9,0,0,0},{20,10,0,0},{11,0,0,0},{12,0,0,0},{13,0,0,0},{13,23,0,0},
  {15,0,0,0},{16,0,0,0},{4,14,0,0},{18,0,0,0},{19,0,0,0},{7,17,0,0},{21,0,0,0},
  {22,0,0,0},{10,20,0,0},{23,0,0,0}};

// column (incoming-edge) structure: sources feeding each state s (pad 0)
__constant__ int c_scnt[32] = {1,1,1,1,2,1,1,3,1,1,4,1,1,2,2,1,1,2,1,1,2,1,1,2,
                               0,0,0,0,0,0,0,0};
__constant__ int4 c_src[32] = {
  {0,0,0,0},{0,0,0,0},{1,0,0,0},{2,0,0,0},{3,16,0,0},{4,0,0,0},{5,0,0,0},
  {3,6,19,0},{7,0,0,0},{8,0,0,0},{3,6,9,22},{10,0,0,0},{11,0,0,0},{12,13,0,0},
  {3,16,0,0},{14,0,0,0},{15,0,0,0},{6,19,0,0},{17,0,0,0},{18,0,0,0},{9,22,0,0},
  {20,0,0,0},{21,0,0,0},{13,23,0,0},
  {0,0,0,0},{0,0,0,0},{0,0,0,0},{0,0,0,0},{0,0,0,0},{0,0,0,0},{0,0,0,0},{0,0,0,0}};

// ---------------------------------------------------------------------------
// Setup: build A (sparse row softmax), per-lane weights W, emission table Bt
// (transposed & padded: Bt[ctx][lane]), and pi.  One small block; runs in ~2us.
// ---------------------------------------------------------------------------
__global__ void setup_kernel(const float* __restrict__ w,
                             const float* __restrict__ ew,
                             const float* __restrict__ ik) {
  __shared__ float V[24][24];
  __shared__ float A[24][24];
  int tid = threadIdx.x;
  for (int i = tid; i < 576; i += blockDim.x) {
    ((float*)V)[i] = 0.f;
    ((float*)A)[i] = 0.f;
  }
  __syncthreads();
  if (tid == 0) {
    float w12 = w[12];
    V[0][0]  = 1.f - w[0]; V[0][1]  = w[0];
    V[1][2]  = 1.f;        V[2][3]  = 1.f;
    V[3][4]  = w[1];       V[6][7]  = w[2];
    V[4][5]  = 1.f; V[7][8] = 1.f; V[5][6] = 1.f; V[8][9] = 1.f;
    V[3][14] = w[3]; V[6][17] = w[4]; V[9][20] = w[5];
    V[9][10] = 1.f - w[5];
    V[14][15] = 1.f; V[17][18] = 1.f; V[20][21] = 1.f;
    V[15][16] = 1.f; V[18][19] = 1.f; V[21][22] = 1.f;
    V[16][4] = w[6]; V[19][7] = w[7]; V[22][10] = w[8];
    V[16][14] = 1.f - w[9]; V[19][17] = 1.f - w[10]; V[22][20] = 1.f - w[11];
    V[3][7]  = 1.f - w12 * w12;
    V[3][10] = 1.f - w12 * w12 * w12;
    V[6][10] = 1.f - w12 * w12;
    V[10][11] = 1.f; V[11][12] = 1.f; V[12][13] = 1.f;
    V[13][13] = 1.f; V[13][23] = 1.f; V[23][23] = 1.f;
  }
  __syncthreads();
  // row softmax over the structural nonzeros (others are exactly 0)
  if (tid < 24) {
    int n = c_rcnt[tid];
    float m = -1e30f;
    for (int i = 0; i < n; ++i) m = fmaxf(m, V[tid][c_rcols[tid][i]]);
    float Z = 0.f;
    for (int i = 0; i < n; ++i) Z += expf(V[tid][c_rcols[tid][i]] - m);
    for (int i = 0; i < n; ++i) {
      int c = c_rcols[tid][i];
      A[tid][c] = expf(V[tid][c] - m) / Z;
    }
  }
  __syncthreads();
  // per-lane incoming-edge weights
  if (tid < 32) {
    float4 wv = make_float4(0.f, 0.f, 0.f, 0.f);
    int n = c_scnt[tid];
    int4 s = c_src[tid];
    if (n > 0) wv.x = A[s.x][tid];
    if (n > 1) wv.y = A[s.y][tid];
    if (n > 2) wv.z = A[s.z][tid];
    if (n > 3) wv.w = A[s.w][tid];
    g_W4[tid] = wv;
  }
  // pi = softmax(init_kernel)
  if (tid == 32) {
    float m = -1e30f;
    for (int s = 0; s < NSTATES; ++s) m = fmaxf(m, ik[s]);
    float Z = 0.f;
    for (int s = 0; s < NSTATES; ++s) Z += expf(ik[s] - m);
    for (int s = 0; s < 32; ++s)
      g_pi[s] = (s < NSTATES) ? expf(ik[s] - m) / Z : 0.f;
  }
  // emission table, transposed: Bt[ctx][lane]; ctx = (pp*6+p)*6+c
  for (int idx = tid; idx < 216 * 32; idx += blockDim.x) {
    int lane = idx & 31, ctx = idx >> 5;
    int pp = ctx / 36, rm = ctx - pp * 36;
    int p = rm / 6, c = rm - p * 6;
    float val = 0.f;
    if (lane < NSTATES) {
      val = 1.f / 6.f;
      if (lane < 17 && pp < 4 && p < 4 && c < 4) {
        const float* e = ew + (((lane * 4) + pp) * 4 + p) * 4;
        float m = fmaxf(fmaxf(e[0], e[1]), fmaxf(e[2], e[3]));
        float Z = expf(e[0] - m) + expf(e[1] - m) + expf(e[2] - m) + expf(e[3] - m);
        val = expf(e[c] - m) / Z;
      }
    }
    g_Bt[idx] = val;
  }
}

// ---------------------------------------------------------------------------
// Forward recurrence: one warp per batch row, lane = state.
// ---------------------------------------------------------------------------
__global__ void __launch_bounds__(32)
fwd_kernel(const int* __restrict__ seq, float* __restrict__ out, int T) {
  const unsigned FULL = 0xffffffffu;
  int lane = threadIdx.x;
  int b = blockIdx.x;
  const int* sq = seq + (long long)b * T;

  float4 W = g_W4[lane];
  int4 S = c_src[lane];
  float alpha = g_pi[lane];

  int s_m2 = 4, s_m1 = 4;  // start-context symbols
  float K = 0.f;           // sum of applied power-of-two exponents
  float pend = 1.0f;       // pending (lagged) scale
  int eK = 0;              // exponent embedded in pend
  int chunk = 0;
  float zlast = 1.0f;

  int nblk = T >> 4;  // T must be a multiple of 16 (2000 = 125*16)

  for (int i = 0; i < nblk; ++i) {
    if ((i & 1) == 0) {
      int idx = (i << 4) + lane;
      chunk = (idx < T) ? sq[idx] : 0;
    }
    int base = (i & 1) << 4;

    // batch all 16 emission loads (independent of the recurrence)
    float E[16];
#pragma unroll
    for (int j = 0; j < 16; ++j) {
      int sym = __shfl_sync(FULL, chunk, base + j);
      int ctx = s_m2 * 36 + s_m1 * 6 + sym;
      s_m2 = s_m1;
      s_m1 = sym;
      E[j] = g_Bt[(ctx << 5) + lane];
    }

    // serial alpha recurrence: sparse matvec via <=4 shfl broadcasts
#pragma unroll
    for (int j = 0; j < 16; ++j) {
      float pred;
      if (j == 0 && i == 0) {
        pred = alpha;  // t=0: pred = pi
      } else {
        float b0 = __shfl_sync(FULL, alpha, S.x);
        float b1 = __shfl_sync(FULL, alpha, S.y);
        float b2 = __shfl_sync(FULL, alpha, S.z);
        float b3 = __shfl_sync(FULL, alpha, S.w);
        pred = fmaf(W.y, b1, W.x * b0) + fmaf(W.w, b3, W.z * b2);
      }
      alpha = pred * E[j];
    }

    // lagged exact power-of-two renorm; butterfly is off the critical path
    alpha *= pend;
    K += (float)eK;
    float z = alpha;
#pragma unroll
    for (int o = 16; o; o >>= 1) z += __shfl_xor_sync(FULL, z, o);
    int ez = ((__float_as_int(z) >> 23) & 0xff) - 127;
    pend = __int_as_float((127 - ez) << 23);  // 2^{-ez}
    eK = ez;
    zlast = z;
  }

  if (lane == 0) out[b] = (__log2f(zlast) + K) * 0.69314718055994530942f;
}

// ---------------------------------------------------------------------------
extern "C" void kernel_launch(void* const* d_in, const int* in_sizes, int n_in,
                              void* d_out, int out_size) {
  const float* w  = (const float*)d_in[0];   // transition_kernel (240)
  const float* ew = (const float*)d_in[1];   // emission_kernel (1088)
  const float* ik = (const float*)d_in[2];   // init_kernel (24)
  const int* seq  = (const int*)d_in[3];     // (batch, T)
  float* out = (float*)d_out;

  int batch = out_size;                      // 2048
  int T = in_sizes[3] / batch;               // 2000

  setup_kernel<<<1, 256>>>(w, ew, ik);
  fwd_kernel<<<batch, 32>>>(seq, out, T);
}

// round 3
// speedup vs baseline: 1.0174x; 1.0174x over previous
#include <cuda_runtime.h>
#include <math.h>

// ---------------------------------------------------------------------------
// HMM forward (CgpHmmCell, nCodons=2): 24 states, CTX=6.
// Layout: 4 batch rows per warp, 8 lanes per row, 3 states per lane.
// Per step: exactly 4 width-8 shfls deliver all cross-lane alpha values.
// Deferred exact power-of-two renormalization every 16 steps.
// ---------------------------------------------------------------------------

#define NSTATES 24

// --- tables built by setup_kernel each launch --------------------------------
__device__ float g_Wl[8][12];        // per-sublane edge weights (11 used)
__device__ float g_Bt4[216 * 32];    // emission float4: [ctx][sub][4] (k=3 pad)
__device__ float g_pi[32];           // softmax(init)

// row softmax structure of A
__constant__ int c_rcnt[24] = {2,1,1,4,1,1,3,1,1,2,1,1,1,2,1,1,2,1,1,2,1,1,2,1};
__constant__ int c_rcols[24][4] = {
  {0,1,0,0},{2,0,0,0},{3,0,0,0},{4,14,7,10},{5,0,0,0},{6,0,0,0},{7,17,10,0},
  {8,0,0,0},{9,0,0,0},{20,10,0,0},{11,0,0,0},{12,0,0,0},{13,0,0,0},{13,23,0,0},
  {15,0,0,0},{16,0,0,0},{4,14,0,0},{18,0,0,0},{19,0,0,0},{7,17,0,0},{21,0,0,0},
  {22,0,0,0},{10,20,0,0},{23,0,0,0}};

// shfl source sublanes (width-8 groups)
__constant__ int c_sr0[8] = {0,0,1,1,1,2,3,0};  // shfl of a0 (first)
__constant__ int c_sr1[8] = {0,0,0,2,0,0,0,0};  // shfl of a0 (second)
__constant__ int c_sr2[8] = {0,5,6,7,5,6,7,4};  // shfl of a1
__constant__ int c_sr3[8] = {0,0,1,2,3,4,5,6};  // shfl of a2

// ---------------------------------------------------------------------------
__global__ void setup_kernel(const float* __restrict__ w,
                             const float* __restrict__ ew,
                             const float* __restrict__ ik) {
  __shared__ float V[24][24];
  __shared__ float A[24][24];
  int tid = threadIdx.x;
  for (int i = tid; i < 576; i += blockDim.x) {
    ((float*)V)[i] = 0.f;
    ((float*)A)[i] = 0.f;
  }
  __syncthreads();
  if (tid == 0) {
    float w12 = w[12];
    V[0][0]  = 1.f - w[0]; V[0][1]  = w[0];
    V[1][2]  = 1.f;        V[2][3]  = 1.f;
    V[3][4]  = w[1];       V[6][7]  = w[2];
    V[4][5]  = 1.f; V[7][8] = 1.f; V[5][6] = 1.f; V[8][9] = 1.f;
    V[3][14] = w[3]; V[6][17] = w[4]; V[9][20] = w[5];
    V[9][10] = 1.f - w[5];
    V[14][15] = 1.f; V[17][18] = 1.f; V[20][21] = 1.f;
    V[15][16] = 1.f; V[18][19] = 1.f; V[21][22] = 1.f;
    V[16][4] = w[6]; V[19][7] = w[7]; V[22][10] = w[8];
    V[16][14] = 1.f - w[9]; V[19][17] = 1.f - w[10]; V[22][20] = 1.f - w[11];
    V[3][7]  = 1.f - w12 * w12;
    V[3][10] = 1.f - w12 * w12 * w12;
    V[6][10] = 1.f - w12 * w12;
    V[10][11] = 1.f; V[11][12] = 1.f; V[12][13] = 1.f;
    V[13][13] = 1.f; V[13][23] = 1.f; V[23][23] = 1.f;
  }
  __syncthreads();
  // row softmax over structural nonzeros
  if (tid < 24) {
    int n = c_rcnt[tid];
    float m = -1e30f;
    for (int i = 0; i < n; ++i) m = fmaxf(m, V[tid][c_rcols[tid][i]]);
    float Z = 0.f;
    for (int i = 0; i < n; ++i) Z += expf(V[tid][c_rcols[tid][i]] - m);
    for (int i = 0; i < n; ++i) {
      int c = c_rcols[tid][i];
      A[tid][c] = expf(V[tid][c] - m) / Z;
    }
  }
  __syncthreads();
  // per-sublane weight table.
  // slots: 0:w0a(r0) 1:w0b(r3) | 2:wa(a0) 3:wb(a1) 4:wc(r0) 5:wd(r1) 6:we(r2)
  //        7:wf(a1) 8:wg(r0) 9:wh(r2) 10:wi(a2)
  if (tid == 0) {
    for (int s = 0; s < 8; ++s)
      for (int k = 0; k < 12; ++k) g_Wl[s][k] = 0.f;
    g_Wl[0][0]=A[0][0];  g_Wl[0][2]=A[0][1];   g_Wl[0][7]=A[1][2];
    g_Wl[1][1]=A[2][3];  g_Wl[1][2]=A[3][4];   g_Wl[1][6]=A[16][4];  g_Wl[1][7]=A[4][5];
    g_Wl[2][1]=A[5][6];  g_Wl[2][4]=A[3][7];   g_Wl[2][2]=A[6][7];   g_Wl[2][6]=A[19][7];  g_Wl[2][7]=A[7][8];
    g_Wl[3][1]=A[8][9];  g_Wl[3][4]=A[3][10];  g_Wl[3][5]=A[6][10];  g_Wl[3][2]=A[9][10];  g_Wl[3][6]=A[22][10]; g_Wl[3][7]=A[10][11];
    g_Wl[4][1]=A[11][12];g_Wl[4][2]=A[12][13]; g_Wl[4][3]=A[13][13]; g_Wl[4][8]=A[3][14];  g_Wl[4][9]=A[16][14];
    g_Wl[5][1]=A[14][15];g_Wl[5][2]=A[15][16]; g_Wl[5][8]=A[6][17];  g_Wl[5][9]=A[19][17];
    g_Wl[6][1]=A[17][18];g_Wl[6][2]=A[18][19]; g_Wl[6][8]=A[9][20];  g_Wl[6][9]=A[22][20];
    g_Wl[7][1]=A[20][21];g_Wl[7][2]=A[21][22]; g_Wl[7][9]=A[13][23]; g_Wl[7][10]=A[23][23];
  }
  // pi = softmax(init)
  if (tid == 32) {
    float m = -1e30f;
    for (int s = 0; s < NSTATES; ++s) m = fmaxf(m, ik[s]);
    float Z = 0.f;
    for (int s = 0; s < NSTATES; ++s) Z += expf(ik[s] - m);
    for (int s = 0; s < 32; ++s)
      g_pi[s] = (s < NSTATES) ? expf(ik[s] - m) / Z : 0.f;
  }
  // emission table: g_Bt4[ctx*32 + sub*4 + k] = B[3*sub+k][ctx], k==3 -> 0
  for (int idx = tid; idx < 216 * 32; idx += blockDim.x) {
    int r = idx & 31, ctx = idx >> 5;
    int sub = r >> 2, k = r & 3;
    int pp = ctx / 36, rm = ctx - pp * 36;
    int p = rm / 6, c = rm - p * 6;
    float val = 0.f;
    if (k < 3) {
      int st = 3 * sub + k;
      val = 1.f / 6.f;
      if (st < 17 && pp < 4 && p < 4 && c < 4) {
        const float* e = ew + (((st * 4) + pp) * 4 + p) * 4;
        float m = fmaxf(fmaxf(e[0], e[1]), fmaxf(e[2], e[3]));
        float Z = expf(e[0] - m) + expf(e[1] - m) + expf(e[2] - m) + expf(e[3] - m);
        val = expf(e[c] - m) / Z;
      }
    }
    g_Bt4[idx] = val;
  }
}

// ---------------------------------------------------------------------------
// Forward: 4 rows/warp, 8 lanes/row, states {3l,3l+1,3l+2} per lane.
// ---------------------------------------------------------------------------
__global__ void __launch_bounds__(32)
fwd_kernel(const int* __restrict__ seq, float* __restrict__ out, int T) {
  const unsigned F = 0xffffffffu;
  int lane = threadIdx.x & 31;
  int sub = lane & 7;
  int row = blockIdx.x * 4 + (lane >> 3);
  const int* sq = seq + (long long)row * T;

  float w0a = g_Wl[sub][0], w0b = g_Wl[sub][1];
  float wa  = g_Wl[sub][2], wb  = g_Wl[sub][3], wc = g_Wl[sub][4];
  float wd  = g_Wl[sub][5], we  = g_Wl[sub][6];
  float wf  = g_Wl[sub][7], wg  = g_Wl[sub][8], wh = g_Wl[sub][9];
  float wi  = g_Wl[sub][10];
  int sr0 = c_sr0[sub], sr1 = c_sr1[sub], sr2 = c_sr2[sub], sr3 = c_sr3[sub];

  float a0 = g_pi[3 * sub + 0];
  float a1 = g_pi[3 * sub + 1];
  float a2 = g_pi[3 * sub + 2];

  const float4* Bt = (const float4*)g_Bt4;  // index: ctx*8 + sub

  int s_m1 = 4, pair = 28;     // start-context (4,4)
  float K = 0.f, pend = 1.f, zlast = 1.f;
  int eK = 0;
  int nblk = T >> 4;           // T = 2000 = 125*16

  for (int i = 0; i < nblk; ++i) {
    // --- fetch 16 symbols (int4 x4, coalesced/broadcast within group) ------
    const int4* sp = (const int4*)(sq + (i << 4));
    int4 sv[4];
#pragma unroll
    for (int q = 0; q < 4; ++q) sv[q] = sp[q];
    int syms[16];
#pragma unroll
    for (int q = 0; q < 4; ++q) {
      syms[4 * q + 0] = sv[q].x; syms[4 * q + 1] = sv[q].y;
      syms[4 * q + 2] = sv[q].z; syms[4 * q + 3] = sv[q].w;
    }

    // --- batch all 16 emission loads (independent of recurrence, MLP=16) ---
    float4 E[16];
#pragma unroll
    for (int j = 0; j < 16; ++j) {
      int sym = syms[j];
      int ctx = pair * 6 + sym;
      pair = s_m1 * 6 + sym;
      s_m1 = sym;
      E[j] = Bt[ctx * 8 + sub];
    }

    // --- serial recurrence: 4 shfls/step, E pre-multiplied into weights ----
#pragma unroll
    for (int j = 0; j < 16; ++j) {
      float E0 = E[j].x, E1 = E[j].y, E2 = E[j].z;
      // cross-lane fetch (in flight while local partials compute)
      float r0 = __shfl_sync(F, a0, sr0, 8);
      float r1 = __shfl_sync(F, a0, sr1, 8);
      float r2 = __shfl_sync(F, a1, sr2, 8);
      float r3 = __shfl_sync(F, a2, sr3, 8);
      // early: fold E into weights + local partial sums
      float d0 = w0a * E0, d1 = w0b * E0;
      float c0 = wc * E1, c1 = wd * E1, c2 = we * E1;
      float g2 = wg * E2, h2 = wh * E2;
      float q1 = E1 * fmaf(wa, a0, wb * a1);
      float q2 = E2 * fmaf(wf, a1, wi * a2);
      // late: combine remotes (short chain after shfl returns)
      float n0 = fmaf(d0, r0, d1 * r3);
      float x1 = fmaf(c0, r0, q1);
      float y1 = fmaf(c1, r1, c2 * r2);
      float n1 = x1 + y1;
      float n2 = fmaf(h2, r2, fmaf(g2, r0, q2));
      if (i == 0 && j == 0) {           // t=0: pred = pi (no transition)
        n0 = a0 * E0; n1 = a1 * E1; n2 = a2 * E2;
      }
      a0 = n0; a1 = n1; a2 = n2;
    }

    // --- lagged exact power-of-two renorm (off critical path) --------------
    a0 *= pend; a1 *= pend; a2 *= pend;
    K += (float)eK;
    float z = a0 + a1 + a2;
#pragma unroll
    for (int o = 4; o; o >>= 1) z += __shfl_xor_sync(F, z, o, 8);
    int ez = ((__float_as_int(z) >> 23) & 0xff) - 127;
    pend = __int_as_float((127 - ez) << 23);  // 2^{-ez}, exact
    eK = ez;
    zlast = z;
  }

  if (sub == 0) out[row] = (__log2f(zlast) + K) * 0.69314718055994530942f;
}

// ---------------------------------------------------------------------------
extern "C" void kernel_launch(void* const* d_in, const int* in_sizes, int n_in,
                              void* d_out, int out_size) {
  const float* w  = (const float*)d_in[0];   // transition_kernel (240)
  const float* ew = (const float*)d_in[1];   // emission_kernel (1088)
  const float* ik = (const float*)d_in[2];   // init_kernel (24)
  const int* seq  = (const int*)d_in[3];     // (batch, T)
  float* out = (float*)d_out;

  int batch = out_size;                      // 2048
  int T = in_sizes[3] / batch;               // 2000

  setup_kernel<<<1, 256>>>(w, ew, ik);
  fwd_kernel<<<batch / 4, 32>>>(seq, out, T);
}

// round 4
// speedup vs baseline: 1.2578x; 1.2363x over previous
#include <cuda_runtime.h>
#include <math.h>

// ---------------------------------------------------------------------------
// HMM forward (CgpHmmCell, nCodons=2): 24 states, CTX=6.
// 4 batch rows per warp, 8 lanes per row, 3 states per lane.
// 4 width-8 shfls per step; E loads double-buffered 4 steps ahead; symbols +
// packed ctx indices prefetched one 16-step block ahead. No register spills.
// Deferred exact power-of-two renormalization every 16 steps.
// ---------------------------------------------------------------------------

#define NSTATES 24

// --- tables built by setup_kernel each launch --------------------------------
__device__ float g_Wl[8][12];        // per-sublane edge weights (11 used)
__device__ float g_Bt4[216 * 32];    // emission float4: [ctx][sub][4] (k=3 pad)
__device__ float g_pi[32];           // softmax(init)

// row softmax structure of A
__constant__ int c_rcnt[24] = {2,1,1,4,1,1,3,1,1,2,1,1,1,2,1,1,2,1,1,2,1,1,2,1};
__constant__ int c_rcols[24][4] = {
  {0,1,0,0},{2,0,0,0},{3,0,0,0},{4,14,7,10},{5,0,0,0},{6,0,0,0},{7,17,10,0},
  {8,0,0,0},{9,0,0,0},{20,10,0,0},{11,0,0,0},{12,0,0,0},{13,0,0,0},{13,23,0,0},
  {15,0,0,0},{16,0,0,0},{4,14,0,0},{18,0,0,0},{19,0,0,0},{7,17,0,0},{21,0,0,0},
  {22,0,0,0},{10,20,0,0},{23,0,0,0}};

// shfl source sublanes (width-8 groups)
__constant__ int c_sr0[8] = {0,0,1,1,1,2,3,0};  // shfl of a0 (first)
__constant__ int c_sr1[8] = {0,0,0,2,0,0,0,0};  // shfl of a0 (second)
__constant__ int c_sr2[8] = {0,5,6,7,5,6,7,4};  // shfl of a1
__constant__ int c_sr3[8] = {0,0,1,2,3,4,5,6};  // shfl of a2

// ---------------------------------------------------------------------------
__global__ void setup_kernel(const float* __restrict__ w,
                             const float* __restrict__ ew,
                             const float* __restrict__ ik) {
  __shared__ float V[24][24];
  __shared__ float A[24][24];
  int tid = threadIdx.x;
  for (int i = tid; i < 576; i += blockDim.x) {
    ((float*)V)[i] = 0.f;
    ((float*)A)[i] = 0.f;
  }
  __syncthreads();
  if (tid == 0) {
    float w12 = w[12];
    V[0][0]  = 1.f - w[0]; V[0][1]  = w[0];
    V[1][2]  = 1.f;        V[2][3]  = 1.f;
    V[3][4]  = w[1];       V[6][7]  = w[2];
    V[4][5]  = 1.f; V[7][8] = 1.f; V[5][6] = 1.f; V[8][9] = 1.f;
    V[3][14] = w[3]; V[6][17] = w[4]; V[9][20] = w[5];
    V[9][10] = 1.f - w[5];
    V[14][15] = 1.f; V[17][18] = 1.f; V[20][21] = 1.f;
    V[15][16] = 1.f; V[18][19] = 1.f; V[21][22] = 1.f;
    V[16][4] = w[6]; V[19][7] = w[7]; V[22][10] = w[8];
    V[16][14] = 1.f - w[9]; V[19][17] = 1.f - w[10]; V[22][20] = 1.f - w[11];
    V[3][7]  = 1.f - w12 * w12;
    V[3][10] = 1.f - w12 * w12 * w12;
    V[6][10] = 1.f - w12 * w12;
    V[10][11] = 1.f; V[11][12] = 1.f; V[12][13] = 1.f;
    V[13][13] = 1.f; V[13][23] = 1.f; V[23][23] = 1.f;
  }
  __syncthreads();
  if (tid < 24) {
    int n = c_rcnt[tid];
    float m = -1e30f;
    for (int i = 0; i < n; ++i) m = fmaxf(m, V[tid][c_rcols[tid][i]]);
    float Z = 0.f;
    for (int i = 0; i < n; ++i) Z += expf(V[tid][c_rcols[tid][i]] - m);
    for (int i = 0; i < n; ++i) {
      int c = c_rcols[tid][i];
      A[tid][c] = expf(V[tid][c] - m) / Z;
    }
  }
  __syncthreads();
  // per-sublane weight table.
  // slots: 0:w0a(r0) 1:w0b(r3) | 2:wa(a0) 3:wb(a1) 4:wc(r0) 5:wd(r1) 6:we(r2)
  //        7:wf(a1) 8:wg(r0) 9:wh(r2) 10:wi(a2)
  if (tid == 0) {
    for (int s = 0; s < 8; ++s)
      for (int k = 0; k < 12; ++k) g_Wl[s][k] = 0.f;
    g_Wl[0][0]=A[0][0];  g_Wl[0][2]=A[0][1];   g_Wl[0][7]=A[1][2];
    g_Wl[1][1]=A[2][3];  g_Wl[1][2]=A[3][4];   g_Wl[1][6]=A[16][4];  g_Wl[1][7]=A[4][5];
    g_Wl[2][1]=A[5][6];  g_Wl[2][4]=A[3][7];   g_Wl[2][2]=A[6][7];   g_Wl[2][6]=A[19][7];  g_Wl[2][7]=A[7][8];
    g_Wl[3][1]=A[8][9];  g_Wl[3][4]=A[3][10];  g_Wl[3][5]=A[6][10];  g_Wl[3][2]=A[9][10];  g_Wl[3][6]=A[22][10]; g_Wl[3][7]=A[10][11];
    g_Wl[4][1]=A[11][12];g_Wl[4][2]=A[12][13]; g_Wl[4][3]=A[13][13]; g_Wl[4][8]=A[3][14];  g_Wl[4][9]=A[16][14];
    g_Wl[5][1]=A[14][15];g_Wl[5][2]=A[15][16]; g_Wl[5][8]=A[6][17];  g_Wl[5][9]=A[19][17];
    g_Wl[6][1]=A[17][18];g_Wl[6][2]=A[18][19]; g_Wl[6][8]=A[9][20];  g_Wl[6][9]=A[22][20];
    g_Wl[7][1]=A[20][21];g_Wl[7][2]=A[21][22]; g_Wl[7][9]=A[13][23]; g_Wl[7][10]=A[23][23];
  }
  if (tid == 32) {
    float m = -1e30f;
    for (int s = 0; s < NSTATES; ++s) m = fmaxf(m, ik[s]);
    float Z = 0.f;
    for (int s = 0; s < NSTATES; ++s) Z += expf(ik[s] - m);
    for (int s = 0; s < 32; ++s)
      g_pi[s] = (s < NSTATES) ? expf(ik[s] - m) / Z : 0.f;
  }
  // emission table: g_Bt4[ctx*32 + sub*4 + k] = B[3*sub+k][ctx], k==3 -> 0
  for (int idx = tid; idx < 216 * 32; idx += blockDim.x) {
    int r = idx & 31, ctx = idx >> 5;
    int sub = r >> 2, k = r & 3;
    int pp = ctx / 36, rm = ctx - pp * 36;
    int p = rm / 6, c = rm - p * 6;
    float val = 0.f;
    if (k < 3) {
      int st = 3 * sub + k;
      val = 1.f / 6.f;
      if (st < 17 && pp < 4 && p < 4 && c < 4) {
        const float* e = ew + (((st * 4) + pp) * 4 + p) * 4;
        float m = fmaxf(fmaxf(e[0], e[1]), fmaxf(e[2], e[3]));
        float Z = expf(e[0] - m) + expf(e[1] - m) + expf(e[2] - m) + expf(e[3] - m);
        val = expf(e[c] - m) / Z;
      }
    }
    g_Bt4[idx] = val;
  }
}

// ---------------------------------------------------------------------------
// Forward: 4 rows/warp, 8 lanes/row, states {3l,3l+1,3l+2} per lane.
// ---------------------------------------------------------------------------

// pack 16 ctx indices (8 bits each) into 4 uints; advances (pair, m1) carry
#define PACKW(dst, sx, sy, sz, sw)                                     \
  {                                                                    \
    int _c0 = pair * 6 + (sx); pair = m1 * 6 + (sx); m1 = (sx);        \
    int _c1 = pair * 6 + (sy); pair = m1 * 6 + (sy); m1 = (sy);        \
    int _c2 = pair * 6 + (sz); pair = m1 * 6 + (sz); m1 = (sz);        \
    int _c3 = pair * 6 + (sw); pair = m1 * 6 + (sw); m1 = (sw);        \
    dst = (unsigned)_c0 | ((unsigned)_c1 << 8) | ((unsigned)_c2 << 16) \
        | ((unsigned)_c3 << 24);                                       \
  }

// issue 4 emission loads for one chunk from a packed-ctx word
#define LOAD4(d0, d1, d2, d3, pk)                       \
  {                                                     \
    unsigned _w = (pk);                                 \
    d0 = Bt[(int)(_w & 255u) * 8 + sub];                \
    d1 = Bt[(int)((_w >> 8) & 255u) * 8 + sub];         \
    d2 = Bt[(int)((_w >> 16) & 255u) * 8 + sub];        \
    d3 = Bt[(int)((_w >> 24) & 255u) * 8 + sub];        \
  }

// one recurrence step
#define STEP(Ev)                                                        \
  {                                                                     \
    float E0 = (Ev).x, E1 = (Ev).y, E2 = (Ev).z;                        \
    float r0 = __shfl_sync(F, a0, sr0, 8);                              \
    float r1 = __shfl_sync(F, a0, sr1, 8);                              \
    float r2 = __shfl_sync(F, a1, sr2, 8);                              \
    float r3 = __shfl_sync(F, a2, sr3, 8);                              \
    float q1 = E1 * fmaf(wa, a0, wb * a1);                              \
    float q2 = E2 * fmaf(wf, a1, wi * a2);                              \
    float n0 = fmaf(w0a * E0, r0, (w0b * E0) * r3);                     \
    float n1 = fmaf(wc * E1, r0, q1) + fmaf(wd * E1, r1, (we * E1) * r2); \
    float n2 = fmaf(wh * E2, r2, fmaf(wg * E2, r0, q2));                \
    a0 = n0; a1 = n1; a2 = n2;                                          \
  }

__global__ void __launch_bounds__(32)
fwd_kernel(const int* __restrict__ seq, float* __restrict__ out, int T) {
  const unsigned F = 0xffffffffu;
  int lane = threadIdx.x & 31;
  int sub = lane & 7;
  int row = blockIdx.x * 4 + (lane >> 3);
  const int4* sp = (const int4*)(seq + (long long)row * T);

  float w0a = g_Wl[sub][0], w0b = g_Wl[sub][1];
  float wa  = g_Wl[sub][2], wb  = g_Wl[sub][3], wc = g_Wl[sub][4];
  float wd  = g_Wl[sub][5], we  = g_Wl[sub][6];
  float wf  = g_Wl[sub][7], wg  = g_Wl[sub][8], wh = g_Wl[sub][9];
  float wi  = g_Wl[sub][10];
  int sr0 = c_sr0[sub], sr1 = c_sr1[sub], sr2 = c_sr2[sub], sr3 = c_sr3[sub];

  float a0 = g_pi[3 * sub + 0];
  float a1 = g_pi[3 * sub + 1];
  float a2 = g_pi[3 * sub + 2];

  const float4* Bt = (const float4*)g_Bt4;  // index: ctx*8 + sub

  int pair = 28, m1 = 4;       // start-context (prev2=4, prev1=4)
  float K = 0.f, pend = 1.f, zlast = 1.f;
  int eK = 0;
  int nblk = T >> 4;           // T = 2000 = 125*16

  // --- prologue: block 0 symbols -> packed ctx; prefetch chunk 0 E ---------
  unsigned cw0, cw1, cw2, cw3;   // current block packed ctx (4 x 4 steps)
  {
    int4 t0 = sp[0], t1 = sp[1], t2 = sp[2], t3 = sp[3];
    PACKW(cw0, t0.x, t0.y, t0.z, t0.w);
    PACKW(cw1, t1.x, t1.y, t1.z, t1.w);
    PACKW(cw2, t2.x, t2.y, t2.z, t2.w);
    PACKW(cw3, t3.x, t3.y, t3.z, t3.w);
  }
  float4 Ea0, Ea1, Ea2, Ea3;     // buffer A (even chunks)
  float4 Eb0, Eb1, Eb2, Eb3;     // buffer B (odd chunks)
  LOAD4(Ea0, Ea1, Ea2, Ea3, cw0);

  for (int i = 0; i < nblk; ++i) {
    // prefetch next block's symbols and pack its ctx (valid carry only if
    // i < nblk-1; last-iteration values are never consumed)
    unsigned nw0, nw1, nw2, nw3;
    {
      int nb = (i + 1 < nblk) ? (i + 1) : 0;
      int4 t0 = sp[nb * 4 + 0], t1 = sp[nb * 4 + 1];
      int4 t2 = sp[nb * 4 + 2], t3 = sp[nb * 4 + 3];
      PACKW(nw0, t0.x, t0.y, t0.z, t0.w);
      PACKW(nw1, t1.x, t1.y, t1.z, t1.w);
      PACKW(nw2, t2.x, t2.y, t2.z, t2.w);
      PACKW(nw3, t3.x, t3.y, t3.z, t3.w);
    }

    // chunk 0 (buffer A); prefetch chunk 1 -> B first
    LOAD4(Eb0, Eb1, Eb2, Eb3, cw1);
    if (i == 0) {                       // t=0: pred = pi (no transition)
      a0 *= Ea0.x; a1 *= Ea0.y; a2 *= Ea0.z;
    } else {
      STEP(Ea0);
    }
    STEP(Ea1); STEP(Ea2); STEP(Ea3);

    // chunk 1 (buffer B); prefetch chunk 2 -> A
    LOAD4(Ea0, Ea1, Ea2, Ea3, cw2);
    STEP(Eb0); STEP(Eb1); STEP(Eb2); STEP(Eb3);

    // chunk 2 (buffer A); prefetch chunk 3 -> B
    LOAD4(Eb0, Eb1, Eb2, Eb3, cw3);
    STEP(Ea0); STEP(Ea1); STEP(Ea2); STEP(Ea3);

    // chunk 3 (buffer B); prefetch next block's chunk 0 -> A
    LOAD4(Ea0, Ea1, Ea2, Ea3, nw0);
    STEP(Eb0); STEP(Eb1); STEP(Eb2); STEP(Eb3);

    // --- lagged exact power-of-two renorm (off critical path) --------------
    a0 *= pend; a1 *= pend; a2 *= pend;
    K += (float)eK;
    float z = a0 + a1 + a2;
#pragma unroll
    for (int o = 4; o; o >>= 1) z += __shfl_xor_sync(F, z, o, 8);
    int ez = ((__float_as_int(z) >> 23) & 0xff) - 127;
    pend = __int_as_float((127 - ez) << 23);  // 2^{-ez}, exact
    eK = ez;
    zlast = z;

    cw0 = nw0; cw1 = nw1; cw2 = nw2; cw3 = nw3;
  }

  if (sub == 0) out[row] = (__log2f(zlast) + K) * 0.69314718055994530942f;
}

// ---------------------------------------------------------------------------
extern "C" void kernel_launch(void* const* d_in, const int* in_sizes, int n_in,
                              void* d_out, int out_size) {
  const float* w  = (const float*)d_in[0];   // transition_kernel (240)
  const float* ew = (const float*)d_in[1];   // emission_kernel (1088)
  const float* ik = (const float*)d_in[2];   // init_kernel (24)
  const int* seq  = (const int*)d_in[3];     // (batch, T)
  float* out = (float*)d_out;

  int batch = out_size;                      // 2048
  int T = in_sizes[3] / batch;               // 2000

  setup_kernel<<<1, 256>>>(w, ew, ik);
  fwd_kernel<<<batch / 4, 32>>>(seq, out, T);
}